// round 8
// baseline (speedup 1.0000x reference)
#include <cuda_runtime.h>
#include <cuda_fp16.h>
#include <math.h>

#define N_NODES 100000
#define N_EDGES 1600000
#define N_GRAPHS 2000
#define IN_C 9
#define HID 256
#define OUTF 128
#define BN_EPS 1e-5f
#define NTRI 45

#define SCAN_B 1024
#define SCAN_NB ((N_NODES + SCAN_B - 1) / SCAN_B)   // 98

// ---------------- scratch ----------------
__device__ float g_dinv[N_NODES];
__device__ int   g_cnt[N_NODES];
__device__ int   g_rowptr[N_NODES + 1];
__device__ int   g_bsum[SCAN_NB];
__device__ int   g_csr_src[N_EDGES];
__device__ float g_csr_w[N_EDGES];
__device__ __align__(16) float  g_xa[N_NODES * IN_C];
__device__ __align__(16) __half g_h1h[N_NODES * HID];   // relu(bn1(h1)), fp16
__device__ __align__(16) __half g_zh [N_NODES * OUTF];  // z, fp16
__device__ __align__(16) __half g_w2h[OUTF * HID];      // W2^T fp16 [n][k]
__device__ __align__(16) float  g_h2[N_NODES * OUTF];
__device__ float g_s[IN_C];
__device__ float g_M[NTRI];
__device__ float g_stat2[2 * OUTF];
__device__ float g_sc1[HID], g_sh1b[HID];   // BN1 affine, b1 folded
__device__ float g_sc2[OUTF], g_sh2[OUTF];
__device__ int   g_gstart[N_GRAPHS + 1];

// ---------------- helpers ----------------
__device__ __forceinline__ void mma_f16(float* d, const unsigned* a, const unsigned* b) {
    asm volatile(
        "mma.sync.aligned.m16n8k16.row.col.f32.f16.f16.f32 "
        "{%0,%1,%2,%3}, {%4,%5,%6,%7}, {%8,%9}, {%0,%1,%2,%3};"
        : "+f"(d[0]), "+f"(d[1]), "+f"(d[2]), "+f"(d[3])
        : "r"(a[0]), "r"(a[1]), "r"(a[2]), "r"(a[3]), "r"(b[0]), "r"(b[1]));
}

// ---------------- kernels ----------------

__global__ void k_count(const int* __restrict__ edge) {
    int e = blockIdx.x * blockDim.x + threadIdx.x;
    if (e >= N_EDGES) return;
    atomicAdd(&g_cnt[edge[N_EDGES + e]], 1);
}

__global__ __launch_bounds__(SCAN_B) void k_scan1() {
    __shared__ int sh[SCAN_B];
    int t = threadIdx.x;
    int i = blockIdx.x * SCAN_B + t;
    int c = (i < N_NODES) ? g_cnt[i] : 0;
    if (i < N_NODES) g_dinv[i] = rsqrtf((float)(c + 1));
    sh[t] = c;
    __syncthreads();
#pragma unroll
    for (int off = 1; off < SCAN_B; off <<= 1) {
        int v = sh[t];
        int add = (t >= off) ? sh[t - off] : 0;
        __syncthreads();
        sh[t] = v + add;
        __syncthreads();
    }
    if (i < N_NODES) g_rowptr[i] = sh[t] - c;
    if (t == SCAN_B - 1) g_bsum[blockIdx.x] = sh[t];
}

__global__ void k_scan2() {
    __shared__ int sh[128];
    int t = threadIdx.x;
    int v = (t < SCAN_NB) ? g_bsum[t] : 0;
    sh[t] = v;
    __syncthreads();
#pragma unroll
    for (int off = 1; off < 128; off <<= 1) {
        int x = sh[t];
        int add = (t >= off) ? sh[t - off] : 0;
        __syncthreads();
        sh[t] = x + add;
        __syncthreads();
    }
    if (t < SCAN_NB) g_bsum[t] = sh[t] - v;
}

__global__ __launch_bounds__(SCAN_B) void k_scan3() {
    int i = blockIdx.x * SCAN_B + threadIdx.x;
    if (i < N_NODES) {
        g_rowptr[i] += g_bsum[blockIdx.x];
        g_cnt[i] = 0;
    }
    if (i == 0) g_rowptr[N_NODES] = N_EDGES;
}

__global__ void k_fill(const int* __restrict__ edge) {
    int e = blockIdx.x * blockDim.x + threadIdx.x;
    if (e >= N_EDGES) return;
    int s = edge[e];
    int d = edge[N_EDGES + e];
    int p = g_rowptr[d] + atomicAdd(&g_cnt[d], 1);
    g_csr_src[p] = s;
    g_csr_w[p] = g_dinv[s];
}

__global__ void k_agg1(const float* __restrict__ x) {
    int n = blockIdx.x * blockDim.x + threadIdx.x;
    if (n >= N_NODES) return;
    float acc[IN_C];
#pragma unroll
    for (int k = 0; k < IN_C; k++) acc[k] = 0.f;
    int s = g_rowptr[n], e = g_rowptr[n + 1];
    for (int p = s; p < e; p++) {
        int sn = g_csr_src[p];
        float w = g_csr_w[p];
        const float* xr = x + (long)sn * IN_C;
#pragma unroll
        for (int k = 0; k < IN_C; k++) acc[k] += w * xr[k];
    }
    float dn = g_dinv[n];
    float d2 = dn * dn;
    const float* xn = x + (long)n * IN_C;
#pragma unroll
    for (int k = 0; k < IN_C; k++) g_xa[n * IN_C + k] = dn * acc[k] + d2 * xn[k];
}

// s = sum(xa), M = upper-tri of sum xa xa^T; also transpose W2 -> fp16 [n][k]
__global__ __launch_bounds__(256) void k_xstat(const float* __restrict__ W2) {
    // W2 transpose (independent work, grid-strided)
    for (int i = blockIdx.x * blockDim.x + threadIdx.x; i < HID * OUTF;
         i += gridDim.x * blockDim.x) {
        int k = i >> 7;         // 0..255
        int n = i & 127;        // 0..127
        g_w2h[n * HID + k] = __float2half(W2[i]);
    }
    float s[IN_C], m[NTRI];
#pragma unroll
    for (int c = 0; c < IN_C; c++) s[c] = 0.f;
#pragma unroll
    for (int i = 0; i < NTRI; i++) m[i] = 0.f;
    for (int n = blockIdx.x * blockDim.x + threadIdx.x; n < N_NODES;
         n += gridDim.x * blockDim.x) {
        float v[IN_C];
#pragma unroll
        for (int c = 0; c < IN_C; c++) v[c] = g_xa[n * IN_C + c];
        int idx = 0;
#pragma unroll
        for (int c = 0; c < IN_C; c++) {
            s[c] += v[c];
#pragma unroll
            for (int d = c; d < IN_C; d++) m[idx++] += v[c] * v[d];
        }
    }
#pragma unroll
    for (int c = 0; c < IN_C; c++)
#pragma unroll
        for (int off = 16; off > 0; off >>= 1)
            s[c] += __shfl_xor_sync(0xffffffffu, s[c], off);
#pragma unroll
    for (int i = 0; i < NTRI; i++)
#pragma unroll
        for (int off = 16; off > 0; off >>= 1)
            m[i] += __shfl_xor_sync(0xffffffffu, m[i], off);
    if ((threadIdx.x & 31) == 0) {
#pragma unroll
        for (int c = 0; c < IN_C; c++) atomicAdd(&g_s[c], s[c]);
#pragma unroll
        for (int i = 0; i < NTRI; i++) atomicAdd(&g_M[i], m[i]);
    }
}

// analytic BN1; zeroes g_s/g_M afterwards (for next graph replay)
__global__ void k_bn1(const float* __restrict__ W1, const float* __restrict__ b1,
                      const float* __restrict__ g1, const float* __restrict__ be1) {
    int j = threadIdx.x;
    float wj[IN_C];
#pragma unroll
    for (int c = 0; c < IN_C; c++) wj[c] = W1[c * HID + j];
    float dot_s = 0.f;
#pragma unroll
    for (int c = 0; c < IN_C; c++) dot_s += g_s[c] * wj[c];
    float q = 0.f;
    int idx = 0;
#pragma unroll
    for (int c = 0; c < IN_C; c++)
#pragma unroll
        for (int d = c; d < IN_C; d++) {
            float coef = (c == d) ? 1.f : 2.f;
            q += coef * g_M[idx++] * wj[c] * wj[d];
        }
    float bj = b1[j];
    float Nf = (float)N_NODES;
    float sum = dot_s + Nf * bj;
    float sq  = q + 2.f * bj * dot_s + Nf * bj * bj;
    float mean = sum / Nf;
    float var = sq / Nf - mean * mean;
    var = fmaxf(var, 0.f);
    float sc = rsqrtf(var + BN_EPS) * g1[j];
    g_sc1[j] = sc;
    g_sh1b[j] = be1[j] - mean * sc + sc * bj;
    __syncthreads();
    if (j < IN_C) g_s[j] = 0.f;
    if (j < NTRI) g_M[j] = 0.f;
}

// h1r = relu(bn1(xa @ W1 + b1)) stored fp16
#define G1_ROWS 64
__global__ __launch_bounds__(256) void k_gemm1(const float* __restrict__ W1) {
    __shared__ float W1s[IN_C * HID];
    __shared__ float xas[G1_ROWS * IN_C];
    int t = threadIdx.x;
    int row0 = blockIdx.x * G1_ROWS;
    for (int i = t; i < IN_C * HID; i += 256) W1s[i] = W1[i];
    for (int i = t; i < G1_ROWS * IN_C; i += 256) {
        int r = row0 + i / IN_C;
        xas[i] = (r < N_NODES) ? g_xa[(long)r * IN_C + (i % IN_C)] : 0.f;
    }
    __syncthreads();
    float sc = g_sc1[t], sh = g_sh1b[t];
    for (int r = 0; r < G1_ROWS; r++) {
        int row = row0 + r;
        if (row >= N_NODES) break;
        float h = 0.f;
#pragma unroll
        for (int k = 0; k < IN_C; k++) h += xas[r * IN_C + k] * W1s[k * HID + t];
        g_h1h[(long)row * HID + t] = __float2half(fmaxf(h * sc + sh, 0.f));
    }
}

// ---- z = h1r @ W2 via fp16 mma m16n8k16; A fp16 (no cvt), B = g_w2h ----
// 128 rows/block, 8 warps, warp = 32 rows x 64 cols. K chunks of 32.
#define TCBM 128
#define TCBK 32
#define SM_S 40   // half stride (20 words), conflict-free fragment loads
__global__ __launch_bounds__(256) void k_gemm2() {
    __shared__ __align__(16) __half As[TCBM * SM_S];   // 10KB
    __shared__ __align__(16) __half Bs[OUTF * SM_S];   // 10KB
    const int t = threadIdx.x;
    const int lane = t & 31;
    const int wid = t >> 5;
    const int gid = lane >> 2;
    const int t4 = lane & 3;
    const int warp_row = (wid & 3) * 32;
    const int warp_col = (wid >> 2) * 64;
    const int row0 = blockIdx.x * TCBM;
    const unsigned* As32 = reinterpret_cast<const unsigned*>(As);
    const unsigned* Bs32 = reinterpret_cast<const unsigned*>(Bs);

    float acc[2][8][4];
#pragma unroll
    for (int r = 0; r < 2; r++)
#pragma unroll
        for (int c = 0; c < 8; c++)
#pragma unroll
            for (int i = 0; i < 4; i++) acc[r][c][i] = 0.f;

    for (int kt = 0; kt < HID / TCBK; kt++) {
        // A chunk: 128 rows x 32 halves, straight uint4 copies
#pragma unroll
        for (int it = 0; it < 2; it++) {
            int q = t + it * 256;
            int row = q >> 2;              // 0..127
            int k8 = (q & 3) * 8;          // 0,8,16,24
            int grow = row0 + row;
            uint4 v = make_uint4(0u, 0u, 0u, 0u);
            if (grow < N_NODES)
                v = *reinterpret_cast<const uint4*>(&g_h1h[(long)grow * HID + kt * TCBK + k8]);
            *reinterpret_cast<uint4*>(&As[row * SM_S + k8]) = v;
        }
        // B chunk: 128 cols x 32 halves from pre-transposed W2
#pragma unroll
        for (int it = 0; it < 2; it++) {
            int q = t + it * 256;
            int n = q >> 2;
            int k8 = (q & 3) * 8;
            uint4 v = *reinterpret_cast<const uint4*>(&g_w2h[n * HID + kt * TCBK + k8]);
            *reinterpret_cast<uint4*>(&Bs[n * SM_S + k8]) = v;
        }
        __syncthreads();
#pragma unroll
        for (int ks = 0; ks < 2; ks++) {       // two k16 steps per chunk
            unsigned a[2][4], b[8][2];
#pragma unroll
            for (int r = 0; r < 2; r++) {
                int rb = (warp_row + r * 16 + gid) * (SM_S / 2) + ks * 8 + t4;
                a[r][0] = As32[rb];
                a[r][1] = As32[rb + 8 * (SM_S / 2)];
                a[r][2] = As32[rb + 4];
                a[r][3] = As32[rb + 8 * (SM_S / 2) + 4];
            }
#pragma unroll
            for (int c = 0; c < 8; c++) {
                int cb = (warp_col + c * 8 + gid) * (SM_S / 2) + ks * 8 + t4;
                b[c][0] = Bs32[cb];
                b[c][1] = Bs32[cb + 4];
            }
#pragma unroll
            for (int r = 0; r < 2; r++)
#pragma unroll
                for (int c = 0; c < 8; c++) mma_f16(acc[r][c], a[r], b[c]);
        }
        __syncthreads();
    }

#pragma unroll
    for (int r = 0; r < 2; r++) {
        int rowA = row0 + warp_row + r * 16 + gid;
        int rowB = rowA + 8;
#pragma unroll
        for (int c = 0; c < 8; c++) {
            int col = warp_col + c * 8 + t4 * 2;
            if (rowA < N_NODES)
                *reinterpret_cast<__half2*>(&g_zh[(long)rowA * OUTF + col]) =
                    __floats2half2_rn(acc[r][c][0], acc[r][c][1]);
            if (rowB < N_NODES)
                *reinterpret_cast<__half2*>(&g_zh[(long)rowB * OUTF + col]) =
                    __floats2half2_rn(acc[r][c][2], acc[r][c][3]);
        }
    }
}

// ---- agg2: warp-per-node, lane covers 4 cols via one LDG.64 gather ----
#define A2_NPW 8
__global__ __launch_bounds__(128) void k_agg2(const float* __restrict__ b2) {
    const int lane = threadIdx.x & 31;
    const int w = threadIdx.x >> 5;
    const int n0 = (blockIdx.x * 4 + w) * A2_NPW;
    const int c0 = lane * 4;
    float4 b2v = reinterpret_cast<const float4*>(b2)[lane];
    float bs[4] = {0.f, 0.f, 0.f, 0.f};
    float bq[4] = {0.f, 0.f, 0.f, 0.f};
#pragma unroll 1
    for (int u = 0; u < A2_NPW; u++) {
        int n = n0 + u;
        int s = g_rowptr[n], e = g_rowptr[n + 1];
        float acc[4] = {0.f, 0.f, 0.f, 0.f};
        int p = s;
        for (; p + 4 <= e; p += 4) {
            int s0 = g_csr_src[p + 0], s1 = g_csr_src[p + 1];
            int s2 = g_csr_src[p + 2], s3 = g_csr_src[p + 3];
            float w0 = g_csr_w[p + 0], w1 = g_csr_w[p + 1];
            float w2 = g_csr_w[p + 2], w3 = g_csr_w[p + 3];
            uint2 r0 = *reinterpret_cast<const uint2*>(&g_zh[(long)s0 * OUTF + c0]);
            uint2 r1 = *reinterpret_cast<const uint2*>(&g_zh[(long)s1 * OUTF + c0]);
            uint2 r2 = *reinterpret_cast<const uint2*>(&g_zh[(long)s2 * OUTF + c0]);
            uint2 r3 = *reinterpret_cast<const uint2*>(&g_zh[(long)s3 * OUTF + c0]);
            float2 a0 = __half22float2(*reinterpret_cast<__half2*>(&r0.x));
            float2 a1 = __half22float2(*reinterpret_cast<__half2*>(&r0.y));
            acc[0] += w0 * a0.x; acc[1] += w0 * a0.y; acc[2] += w0 * a1.x; acc[3] += w0 * a1.y;
            a0 = __half22float2(*reinterpret_cast<__half2*>(&r1.x));
            a1 = __half22float2(*reinterpret_cast<__half2*>(&r1.y));
            acc[0] += w1 * a0.x; acc[1] += w1 * a0.y; acc[2] += w1 * a1.x; acc[3] += w1 * a1.y;
            a0 = __half22float2(*reinterpret_cast<__half2*>(&r2.x));
            a1 = __half22float2(*reinterpret_cast<__half2*>(&r2.y));
            acc[0] += w2 * a0.x; acc[1] += w2 * a0.y; acc[2] += w2 * a1.x; acc[3] += w2 * a1.y;
            a0 = __half22float2(*reinterpret_cast<__half2*>(&r3.x));
            a1 = __half22float2(*reinterpret_cast<__half2*>(&r3.y));
            acc[0] += w3 * a0.x; acc[1] += w3 * a0.y; acc[2] += w3 * a1.x; acc[3] += w3 * a1.y;
        }
        for (; p < e; p++) {
            int sn = g_csr_src[p];
            float ww = g_csr_w[p];
            uint2 r0 = *reinterpret_cast<const uint2*>(&g_zh[(long)sn * OUTF + c0]);
            float2 a0 = __half22float2(*reinterpret_cast<__half2*>(&r0.x));
            float2 a1 = __half22float2(*reinterpret_cast<__half2*>(&r0.y));
            acc[0] += ww * a0.x; acc[1] += ww * a0.y; acc[2] += ww * a1.x; acc[3] += ww * a1.y;
        }
        float dn = g_dinv[n];
        float d2 = dn * dn;
        uint2 rs = *reinterpret_cast<const uint2*>(&g_zh[(long)n * OUTF + c0]);
        float2 z0 = __half22float2(*reinterpret_cast<__half2*>(&rs.x));
        float2 z1 = __half22float2(*reinterpret_cast<__half2*>(&rs.y));
        float v0 = dn * acc[0] + d2 * z0.x + b2v.x;
        float v1 = dn * acc[1] + d2 * z0.y + b2v.y;
        float v2 = dn * acc[2] + d2 * z1.x + b2v.z;
        float v3 = dn * acc[3] + d2 * z1.y + b2v.w;
        *reinterpret_cast<float4*>(&g_h2[(long)n * OUTF + c0]) = make_float4(v0, v1, v2, v3);
        bs[0] += v0; bs[1] += v1; bs[2] += v2; bs[3] += v3;
        bq[0] += v0 * v0; bq[1] += v1 * v1; bq[2] += v2 * v2; bq[3] += v3 * v3;
    }
#pragma unroll
    for (int i = 0; i < 4; i++) {
        atomicAdd(&g_stat2[c0 + i], bs[i]);
        atomicAdd(&g_stat2[OUTF + c0 + i], bq[i]);
    }
}

// BN2 affine; zeroes g_stat2 afterwards
__global__ void k_bn2(const float* __restrict__ g2, const float* __restrict__ be2) {
    int j = threadIdx.x;
    float su = g_stat2[j], sq = g_stat2[OUTF + j];
    float mean = su / (float)N_NODES;
    float var = sq / (float)N_NODES - mean * mean;
    var = fmaxf(var, 0.f);
    float sc = rsqrtf(var + BN_EPS) * g2[j];
    g_sc2[j] = sc;
    g_sh2[j] = be2[j] - mean * sc;
    __syncthreads();
    g_stat2[j] = 0.f;
    g_stat2[OUTF + j] = 0.f;
}

// graph starts; also re-zero g_cnt for next replay's k_count
__global__ void k_gstart(const int* __restrict__ batch) {
    int i = blockIdx.x * blockDim.x + threadIdx.x;
    if (i > N_NODES) return;
    if (i < N_NODES) g_cnt[i] = 0;
    int b = (i < N_NODES) ? batch[i] : N_GRAPHS;
    int bp = (i > 0) ? batch[i - 1] : -1;
    for (int g = bp + 1; g <= b && g <= N_GRAPHS; g++) g_gstart[g] = i;
}

__global__ __launch_bounds__(128) void k_pool(float* __restrict__ out) {
    int g = blockIdx.x;
    int j = threadIdx.x;
    int s = g_gstart[g], e = g_gstart[g + 1];
    float acc = 0.f;
    for (int i = s; i < e; i++) acc += g_h2[(long)i * OUTF + j];
    int cnt = e - s;
    float y = 0.f;
    if (cnt > 0) {
        float p = acc / (float)cnt;
        y = p * g_sc2[j] + g_sh2[j];
    }
    float v = y * y;
#pragma unroll
    for (int off = 16; off > 0; off >>= 1) v += __shfl_xor_sync(0xffffffffu, v, off);
    __shared__ float ws[4];
    if ((j & 31) == 0) ws[j >> 5] = v;
    __syncthreads();
    float ss = ws[0] + ws[1] + ws[2] + ws[3];
    float nrm = sqrtf(ss);
    out[g * OUTF + j] = y / fmaxf(nrm, 1e-12f);
}

// ---------------- launch ----------------
extern "C" void kernel_launch(void* const* d_in, const int* in_sizes, int n_in,
                              void* d_out, int out_size) {
    const float* x   = (const float*)d_in[0];
    const float* W1  = (const float*)d_in[1];
    const float* b1  = (const float*)d_in[2];
    const float* g1  = (const float*)d_in[3];
    const float* be1 = (const float*)d_in[4];
    const float* W2  = (const float*)d_in[5];
    const float* b2  = (const float*)d_in[6];
    const float* g2  = (const float*)d_in[7];
    const float* be2 = (const float*)d_in[8];
    const int* edge  = (const int*)d_in[9];
    const int* batch = (const int*)d_in[10];
    float* out = (float*)d_out;

    const int TB = 256;
    int nb_N = (N_NODES + TB - 1) / TB;
    int nb_E = (N_EDGES + TB - 1) / TB;

    k_count<<<nb_E, TB>>>(edge);
    k_scan1<<<SCAN_NB, SCAN_B>>>();
    k_scan2<<<1, 128>>>();
    k_scan3<<<SCAN_NB, SCAN_B>>>();
    k_fill<<<nb_E, TB>>>(edge);
    k_agg1<<<nb_N, TB>>>(x);
    k_xstat<<<148, 256>>>(W2);
    k_bn1<<<1, HID>>>(W1, b1, g1, be1);
    k_gemm1<<<(N_NODES + G1_ROWS - 1) / G1_ROWS, 256>>>(W1);
    k_gemm2<<<(N_NODES + TCBM - 1) / TCBM, 256>>>();
    k_agg2<<<N_NODES / (4 * A2_NPW), 128>>>(b2);
    k_bn2<<<1, OUTF>>>(g2, be2);
    k_gstart<<<(N_NODES + 1 + TB - 1) / TB, TB>>>(batch);
    k_pool<<<N_GRAPHS, 128>>>(out);
}

// round 9
// speedup vs baseline: 1.5906x; 1.5906x over previous
#include <cuda_runtime.h>
#include <cuda_fp16.h>
#include <math.h>

#define N_NODES 100000
#define N_EDGES 1600000
#define N_GRAPHS 2000
#define IN_C 9
#define HID 256
#define OUTF 128
#define BN_EPS 1e-5f
#define NTRI 45

#define SCAN_B 1024
#define SCAN_NB ((N_NODES + SCAN_B - 1) / SCAN_B)   // 98

// ---------------- scratch ----------------
__device__ float g_dinv[N_NODES];
__device__ int   g_cnt[N_NODES];
__device__ int   g_rowptr[N_NODES + 1];
__device__ int   g_bsum[SCAN_NB];
__device__ int   g_csr_src[N_EDGES];
__device__ float g_csr_w[N_EDGES];
__device__ __align__(16) float  g_xa[N_NODES * IN_C];
__device__ __align__(16) __half g_h1h[N_NODES * HID];   // relu(bn1(h1)), fp16
__device__ __align__(16) __half g_zh [N_NODES * OUTF];  // z, fp16
__device__ __align__(16) __half g_w2h[OUTF * HID];      // W2^T fp16 [n][k]
__device__ __align__(16) float  g_h2[N_NODES * OUTF];
__device__ float g_s[IN_C];
__device__ float g_M[NTRI];
__device__ float g_stat2[2 * OUTF];
__device__ float g_sc1[HID], g_sh1b[HID];   // BN1 affine, b1 folded
__device__ float g_sc2[OUTF], g_sh2[OUTF];
__device__ int   g_gstart[N_GRAPHS + 1];

// ---------------- helpers ----------------
__device__ __forceinline__ void mma_f16(float* d, const unsigned* a, const unsigned* b) {
    asm volatile(
        "mma.sync.aligned.m16n8k16.row.col.f32.f16.f16.f32 "
        "{%0,%1,%2,%3}, {%4,%5,%6,%7}, {%8,%9}, {%0,%1,%2,%3};"
        : "+f"(d[0]), "+f"(d[1]), "+f"(d[2]), "+f"(d[3])
        : "r"(a[0]), "r"(a[1]), "r"(a[2]), "r"(a[3]), "r"(b[0]), "r"(b[1]));
}

// ---------------- kernels ----------------

__global__ void k_count(const int* __restrict__ edge) {
    int e = blockIdx.x * blockDim.x + threadIdx.x;
    if (e >= N_EDGES) return;
    atomicAdd(&g_cnt[edge[N_EDGES + e]], 1);
}

__global__ __launch_bounds__(SCAN_B) void k_scan1() {
    __shared__ int sh[SCAN_B];
    int t = threadIdx.x;
    int i = blockIdx.x * SCAN_B + t;
    int c = (i < N_NODES) ? g_cnt[i] : 0;
    if (i < N_NODES) g_dinv[i] = rsqrtf((float)(c + 1));
    sh[t] = c;
    __syncthreads();
#pragma unroll
    for (int off = 1; off < SCAN_B; off <<= 1) {
        int v = sh[t];
        int add = (t >= off) ? sh[t - off] : 0;
        __syncthreads();
        sh[t] = v + add;
        __syncthreads();
    }
    if (i < N_NODES) g_rowptr[i] = sh[t] - c;
    if (t == SCAN_B - 1) g_bsum[blockIdx.x] = sh[t];
}

__global__ void k_scan2() {
    __shared__ int sh[128];
    int t = threadIdx.x;
    int v = (t < SCAN_NB) ? g_bsum[t] : 0;
    sh[t] = v;
    __syncthreads();
#pragma unroll
    for (int off = 1; off < 128; off <<= 1) {
        int x = sh[t];
        int add = (t >= off) ? sh[t - off] : 0;
        __syncthreads();
        sh[t] = x + add;
        __syncthreads();
    }
    if (t < SCAN_NB) g_bsum[t] = sh[t] - v;
}

__global__ __launch_bounds__(SCAN_B) void k_scan3() {
    int i = blockIdx.x * SCAN_B + threadIdx.x;
    if (i < N_NODES) {
        g_rowptr[i] += g_bsum[blockIdx.x];
        g_cnt[i] = 0;
    }
    if (i == 0) g_rowptr[N_NODES] = N_EDGES;
}

__global__ void k_fill(const int* __restrict__ edge) {
    int e = blockIdx.x * blockDim.x + threadIdx.x;
    if (e >= N_EDGES) return;
    int s = edge[e];
    int d = edge[N_EDGES + e];
    int p = g_rowptr[d] + atomicAdd(&g_cnt[d], 1);
    g_csr_src[p] = s;
    g_csr_w[p] = g_dinv[s];
}

__global__ void k_agg1(const float* __restrict__ x) {
    int n = blockIdx.x * blockDim.x + threadIdx.x;
    if (n >= N_NODES) return;
    float acc[IN_C];
#pragma unroll
    for (int k = 0; k < IN_C; k++) acc[k] = 0.f;
    int s = g_rowptr[n], e = g_rowptr[n + 1];
    for (int p = s; p < e; p++) {
        int sn = g_csr_src[p];
        float w = g_csr_w[p];
        const float* xr = x + (long)sn * IN_C;
#pragma unroll
        for (int k = 0; k < IN_C; k++) acc[k] += w * xr[k];
    }
    float dn = g_dinv[n];
    float d2 = dn * dn;
    const float* xn = x + (long)n * IN_C;
#pragma unroll
    for (int k = 0; k < IN_C; k++) g_xa[n * IN_C + k] = dn * acc[k] + d2 * xn[k];
}

// s = sum(xa), M = upper-tri of sum xa xa^T; also transpose W2 -> fp16 [n][k]
__global__ __launch_bounds__(256) void k_xstat(const float* __restrict__ W2) {
    for (int i = blockIdx.x * blockDim.x + threadIdx.x; i < HID * OUTF;
         i += gridDim.x * blockDim.x) {
        int k = i >> 7;
        int n = i & 127;
        g_w2h[n * HID + k] = __float2half(W2[i]);
    }
    float s[IN_C], m[NTRI];
#pragma unroll
    for (int c = 0; c < IN_C; c++) s[c] = 0.f;
#pragma unroll
    for (int i = 0; i < NTRI; i++) m[i] = 0.f;
    for (int n = blockIdx.x * blockDim.x + threadIdx.x; n < N_NODES;
         n += gridDim.x * blockDim.x) {
        float v[IN_C];
#pragma unroll
        for (int c = 0; c < IN_C; c++) v[c] = g_xa[n * IN_C + c];
        int idx = 0;
#pragma unroll
        for (int c = 0; c < IN_C; c++) {
            s[c] += v[c];
#pragma unroll
            for (int d = c; d < IN_C; d++) m[idx++] += v[c] * v[d];
        }
    }
#pragma unroll
    for (int c = 0; c < IN_C; c++)
#pragma unroll
        for (int off = 16; off > 0; off >>= 1)
            s[c] += __shfl_xor_sync(0xffffffffu, s[c], off);
#pragma unroll
    for (int i = 0; i < NTRI; i++)
#pragma unroll
        for (int off = 16; off > 0; off >>= 1)
            m[i] += __shfl_xor_sync(0xffffffffu, m[i], off);
    if ((threadIdx.x & 31) == 0) {
#pragma unroll
        for (int c = 0; c < IN_C; c++) atomicAdd(&g_s[c], s[c]);
#pragma unroll
        for (int i = 0; i < NTRI; i++) atomicAdd(&g_M[i], m[i]);
    }
}

// analytic BN1; zeroes g_s/g_M afterwards
__global__ void k_bn1(const float* __restrict__ W1, const float* __restrict__ b1,
                      const float* __restrict__ g1, const float* __restrict__ be1) {
    int j = threadIdx.x;
    float wj[IN_C];
#pragma unroll
    for (int c = 0; c < IN_C; c++) wj[c] = W1[c * HID + j];
    float dot_s = 0.f;
#pragma unroll
    for (int c = 0; c < IN_C; c++) dot_s += g_s[c] * wj[c];
    float q = 0.f;
    int idx = 0;
#pragma unroll
    for (int c = 0; c < IN_C; c++)
#pragma unroll
        for (int d = c; d < IN_C; d++) {
            float coef = (c == d) ? 1.f : 2.f;
            q += coef * g_M[idx++] * wj[c] * wj[d];
        }
    float bj = b1[j];
    float Nf = (float)N_NODES;
    float sum = dot_s + Nf * bj;
    float sq  = q + 2.f * bj * dot_s + Nf * bj * bj;
    float mean = sum / Nf;
    float var = sq / Nf - mean * mean;
    var = fmaxf(var, 0.f);
    float sc = rsqrtf(var + BN_EPS) * g1[j];
    g_sc1[j] = sc;
    g_sh1b[j] = be1[j] - mean * sc + sc * bj;
    __syncthreads();
    if (j < IN_C) g_s[j] = 0.f;
    if (j < NTRI) g_M[j] = 0.f;
}

// h1r = relu(bn1(xa @ W1 + b1)) stored fp16
#define G1_ROWS 64
__global__ __launch_bounds__(256) void k_gemm1(const float* __restrict__ W1) {
    __shared__ float W1s[IN_C * HID];
    __shared__ float xas[G1_ROWS * IN_C];
    int t = threadIdx.x;
    int row0 = blockIdx.x * G1_ROWS;
    for (int i = t; i < IN_C * HID; i += 256) W1s[i] = W1[i];
    for (int i = t; i < G1_ROWS * IN_C; i += 256) {
        int r = row0 + i / IN_C;
        xas[i] = (r < N_NODES) ? g_xa[(long)r * IN_C + (i % IN_C)] : 0.f;
    }
    __syncthreads();
    float sc = g_sc1[t], sh = g_sh1b[t];
    for (int r = 0; r < G1_ROWS; r++) {
        int row = row0 + r;
        if (row >= N_NODES) break;
        float h = 0.f;
#pragma unroll
        for (int k = 0; k < IN_C; k++) h += xas[r * IN_C + k] * W1s[k * HID + t];
        g_h1h[(long)row * HID + t] = __float2half(fmaxf(h * sc + sh, 0.f));
    }
}

// ---- z = h1r @ W2 via fp16 mma m16n8k16 ----
#define TCBM 128
#define TCBK 32
#define SM_S 40
__global__ __launch_bounds__(256) void k_gemm2() {
    __shared__ __align__(16) __half As[TCBM * SM_S];
    __shared__ __align__(16) __half Bs[OUTF * SM_S];
    const int t = threadIdx.x;
    const int lane = t & 31;
    const int wid = t >> 5;
    const int gid = lane >> 2;
    const int t4 = lane & 3;
    const int warp_row = (wid & 3) * 32;
    const int warp_col = (wid >> 2) * 64;
    const int row0 = blockIdx.x * TCBM;
    const unsigned* As32 = reinterpret_cast<const unsigned*>(As);
    const unsigned* Bs32 = reinterpret_cast<const unsigned*>(Bs);

    float acc[2][8][4];
#pragma unroll
    for (int r = 0; r < 2; r++)
#pragma unroll
        for (int c = 0; c < 8; c++)
#pragma unroll
            for (int i = 0; i < 4; i++) acc[r][c][i] = 0.f;

    for (int kt = 0; kt < HID / TCBK; kt++) {
#pragma unroll
        for (int it = 0; it < 2; it++) {
            int q = t + it * 256;
            int row = q >> 2;
            int k8 = (q & 3) * 8;
            int grow = row0 + row;
            uint4 v = make_uint4(0u, 0u, 0u, 0u);
            if (grow < N_NODES)
                v = *reinterpret_cast<const uint4*>(&g_h1h[(long)grow * HID + kt * TCBK + k8]);
            *reinterpret_cast<uint4*>(&As[row * SM_S + k8]) = v;
        }
#pragma unroll
        for (int it = 0; it < 2; it++) {
            int q = t + it * 256;
            int n = q >> 2;
            int k8 = (q & 3) * 8;
            uint4 v = *reinterpret_cast<const uint4*>(&g_w2h[n * HID + kt * TCBK + k8]);
            *reinterpret_cast<uint4*>(&Bs[n * SM_S + k8]) = v;
        }
        __syncthreads();
#pragma unroll
        for (int ks = 0; ks < 2; ks++) {
            unsigned a[2][4], b[8][2];
#pragma unroll
            for (int r = 0; r < 2; r++) {
                int rb = (warp_row + r * 16 + gid) * (SM_S / 2) + ks * 8 + t4;
                a[r][0] = As32[rb];
                a[r][1] = As32[rb + 8 * (SM_S / 2)];
                a[r][2] = As32[rb + 4];
                a[r][3] = As32[rb + 8 * (SM_S / 2) + 4];
            }
#pragma unroll
            for (int c = 0; c < 8; c++) {
                int cb = (warp_col + c * 8 + gid) * (SM_S / 2) + ks * 8 + t4;
                b[c][0] = Bs32[cb];
                b[c][1] = Bs32[cb + 4];
            }
#pragma unroll
            for (int r = 0; r < 2; r++)
#pragma unroll
                for (int c = 0; c < 8; c++) mma_f16(acc[r][c], a[r], b[c]);
        }
        __syncthreads();
    }

#pragma unroll
    for (int r = 0; r < 2; r++) {
        int rowA = row0 + warp_row + r * 16 + gid;
        int rowB = rowA + 8;
#pragma unroll
        for (int c = 0; c < 8; c++) {
            int col = warp_col + c * 8 + t4 * 2;
            if (rowA < N_NODES)
                *reinterpret_cast<__half2*>(&g_zh[(long)rowA * OUTF + col]) =
                    __floats2half2_rn(acc[r][c][0], acc[r][c][1]);
            if (rowB < N_NODES)
                *reinterpret_cast<__half2*>(&g_zh[(long)rowB * OUTF + col]) =
                    __floats2half2_rn(acc[r][c][2], acc[r][c][3]);
        }
    }
}

// ---- agg2: thread-per-column (128 cols), 4 nodes/block, 8-edge MLP batch ----
#define A2_NPB 4
__global__ __launch_bounds__(128) void k_agg2(const float* __restrict__ b2) {
    int j = threadIdx.x;
    int n0 = blockIdx.x * A2_NPB;
    float b2j = b2[j];
    float bs = 0.f, bq = 0.f;
#pragma unroll 1
    for (int u = 0; u < A2_NPB; u++) {
        int n = n0 + u;
        int s = g_rowptr[n], e = g_rowptr[n + 1];
        float acc = 0.f;
        int p = s;
        for (; p + 8 <= e; p += 8) {
            int sn[8]; float w[8]; float zv[8];
#pragma unroll
            for (int q = 0; q < 8; q++) { sn[q] = g_csr_src[p + q]; w[q] = g_csr_w[p + q]; }
#pragma unroll
            for (int q = 0; q < 8; q++) zv[q] = __half2float(g_zh[(long)sn[q] * OUTF + j]);
#pragma unroll
            for (int q = 0; q < 8; q++) acc += w[q] * zv[q];
        }
        for (; p < e; p++)
            acc += g_csr_w[p] * __half2float(g_zh[(long)g_csr_src[p] * OUTF + j]);
        float dn = g_dinv[n];
        float val = dn * acc + dn * dn * __half2float(g_zh[(long)n * OUTF + j]) + b2j;
        g_h2[(long)n * OUTF + j] = val;
        bs += val;
        bq += val * val;
    }
    atomicAdd(&g_stat2[j], bs);
    atomicAdd(&g_stat2[OUTF + j], bq);
}

// BN2 affine; zeroes g_stat2 afterwards
__global__ void k_bn2(const float* __restrict__ g2, const float* __restrict__ be2) {
    int j = threadIdx.x;
    float su = g_stat2[j], sq = g_stat2[OUTF + j];
    float mean = su / (float)N_NODES;
    float var = sq / (float)N_NODES - mean * mean;
    var = fmaxf(var, 0.f);
    float sc = rsqrtf(var + BN_EPS) * g2[j];
    g_sc2[j] = sc;
    g_sh2[j] = be2[j] - mean * sc;
    __syncthreads();
    g_stat2[j] = 0.f;
    g_stat2[OUTF + j] = 0.f;
}

// graph starts; also re-zero g_cnt for next replay's k_count
__global__ void k_gstart(const int* __restrict__ batch) {
    int i = blockIdx.x * blockDim.x + threadIdx.x;
    if (i > N_NODES) return;
    if (i < N_NODES) g_cnt[i] = 0;
    int b = (i < N_NODES) ? batch[i] : N_GRAPHS;
    int bp = (i > 0) ? batch[i - 1] : -1;
    for (int g = bp + 1; g <= b && g <= N_GRAPHS; g++) g_gstart[g] = i;
}

__global__ __launch_bounds__(128) void k_pool(float* __restrict__ out) {
    int g = blockIdx.x;
    int j = threadIdx.x;
    int s = g_gstart[g], e = g_gstart[g + 1];
    float acc = 0.f;
    for (int i = s; i < e; i++) acc += g_h2[(long)i * OUTF + j];
    int cnt = e - s;
    float y = 0.f;
    if (cnt > 0) {
        float p = acc / (float)cnt;
        y = p * g_sc2[j] + g_sh2[j];
    }
    float v = y * y;
#pragma unroll
    for (int off = 16; off > 0; off >>= 1) v += __shfl_xor_sync(0xffffffffu, v, off);
    __shared__ float ws[4];
    if ((j & 31) == 0) ws[j >> 5] = v;
    __syncthreads();
    float ss = ws[0] + ws[1] + ws[2] + ws[3];
    float nrm = sqrtf(ss);
    out[g * OUTF + j] = y / fmaxf(nrm, 1e-12f);
}

// ---------------- launch ----------------
extern "C" void kernel_launch(void* const* d_in, const int* in_sizes, int n_in,
                              void* d_out, int out_size) {
    const float* x   = (const float*)d_in[0];
    const float* W1  = (const float*)d_in[1];
    const float* b1  = (const float*)d_in[2];
    const float* g1  = (const float*)d_in[3];
    const float* be1 = (const float*)d_in[4];
    const float* W2  = (const float*)d_in[5];
    const float* b2  = (const float*)d_in[6];
    const float* g2  = (const float*)d_in[7];
    const float* be2 = (const float*)d_in[8];
    const int* edge  = (const int*)d_in[9];
    const int* batch = (const int*)d_in[10];
    float* out = (float*)d_out;

    const int TB = 256;
    int nb_N = (N_NODES + TB - 1) / TB;
    int nb_E = (N_EDGES + TB - 1) / TB;

    k_count<<<nb_E, TB>>>(edge);
    k_scan1<<<SCAN_NB, SCAN_B>>>();
    k_scan2<<<1, 128>>>();
    k_scan3<<<SCAN_NB, SCAN_B>>>();
    k_fill<<<nb_E, TB>>>(edge);
    k_agg1<<<nb_N, TB>>>(x);
    k_xstat<<<148, 256>>>(W2);
    k_bn1<<<1, HID>>>(W1, b1, g1, be1);
    k_gemm1<<<(N_NODES + G1_ROWS - 1) / G1_ROWS, 256>>>(W1);
    k_gemm2<<<(N_NODES + TCBM - 1) / TCBM, 256>>>();
    k_agg2<<<N_NODES / A2_NPB, 128>>>(b2);
    k_bn2<<<1, OUTF>>>(g2, be2);
    k_gstart<<<(N_NODES + 1 + TB - 1) / TB, TB>>>(batch);
    k_pool<<<N_GRAPHS, 128>>>(out);
}

// round 10
// speedup vs baseline: 2.0301x; 1.2763x over previous
#include <cuda_runtime.h>
#include <cuda_fp16.h>
#include <math.h>

#define N_NODES 100000
#define N_EDGES 1600000
#define N_GRAPHS 2000
#define IN_C 9
#define HID 256
#define OUTF 128
#define BN_EPS 1e-5f

#define SCAN_B 1024
#define SCAN_NB ((N_NODES + SCAN_B - 1) / SCAN_B)   // 98

// ---------------- scratch ----------------
__device__ float g_dinv[N_NODES];
__device__ int   g_cnt[N_NODES];
__device__ int   g_rowptr[N_NODES + 1];
__device__ int   g_bsum[SCAN_NB];
__device__ int   g_csr_src[N_EDGES];
__device__ float g_csr_w[N_EDGES];
__device__ float g_xa[N_NODES * IN_C];
__device__ __align__(16) float  g_h1[N_NODES * HID];
__device__ __align__(16) __half g_zh[N_NODES * OUTF];   // z in fp16 (sole delta vs R5)
__device__ __align__(16) float  g_h2[N_NODES * OUTF];
__device__ float g_stat1[2 * HID];
__device__ float g_stat2[2 * OUTF];
__device__ float g_sc1[HID], g_sh1[HID];
__device__ float g_sc2[OUTF], g_sh2[OUTF];
__device__ int   g_gstart[N_GRAPHS + 1];

// ---------------- helpers ----------------
__device__ __forceinline__ unsigned f2tf(float f) {
    unsigned r;
    asm("cvt.rna.tf32.f32 %0, %1;" : "=r"(r) : "f"(f));
    return r;
}
__device__ __forceinline__ void mma_tf32(float* d, const unsigned* a, const unsigned* b) {
    asm volatile(
        "mma.sync.aligned.m16n8k8.row.col.f32.tf32.tf32.f32 "
        "{%0,%1,%2,%3}, {%4,%5,%6,%7}, {%8,%9}, {%0,%1,%2,%3};"
        : "+f"(d[0]), "+f"(d[1]), "+f"(d[2]), "+f"(d[3])
        : "r"(a[0]), "r"(a[1]), "r"(a[2]), "r"(a[3]), "r"(b[0]), "r"(b[1]));
}

// ---------------- kernels ----------------

__global__ void k_init() {
    int i = blockIdx.x * blockDim.x + threadIdx.x;
    if (i < N_NODES) g_cnt[i] = 0;
    if (i < 2 * HID) g_stat1[i] = 0.f;
    if (i < 2 * OUTF) g_stat2[i] = 0.f;
}

__global__ void k_count(const int* __restrict__ edge) {
    int e = blockIdx.x * blockDim.x + threadIdx.x;
    if (e >= N_EDGES) return;
    atomicAdd(&g_cnt[edge[N_EDGES + e]], 1);
}

__global__ __launch_bounds__(SCAN_B) void k_scan1() {
    __shared__ int sh[SCAN_B];
    int t = threadIdx.x;
    int i = blockIdx.x * SCAN_B + t;
    int c = (i < N_NODES) ? g_cnt[i] : 0;
    if (i < N_NODES) g_dinv[i] = rsqrtf((float)(c + 1));
    sh[t] = c;
    __syncthreads();
#pragma unroll
    for (int off = 1; off < SCAN_B; off <<= 1) {
        int v = sh[t];
        int add = (t >= off) ? sh[t - off] : 0;
        __syncthreads();
        sh[t] = v + add;
        __syncthreads();
    }
    if (i < N_NODES) g_rowptr[i] = sh[t] - c;
    if (t == SCAN_B - 1) g_bsum[blockIdx.x] = sh[t];
}

__global__ void k_scan2() {
    __shared__ int sh[128];
    int t = threadIdx.x;
    int v = (t < SCAN_NB) ? g_bsum[t] : 0;
    sh[t] = v;
    __syncthreads();
#pragma unroll
    for (int off = 1; off < 128; off <<= 1) {
        int x = sh[t];
        int add = (t >= off) ? sh[t - off] : 0;
        __syncthreads();
        sh[t] = x + add;
        __syncthreads();
    }
    if (t < SCAN_NB) g_bsum[t] = sh[t] - v;
}

__global__ __launch_bounds__(SCAN_B) void k_scan3() {
    int i = blockIdx.x * SCAN_B + threadIdx.x;
    if (i < N_NODES) {
        g_rowptr[i] += g_bsum[blockIdx.x];
        g_cnt[i] = 0;
    }
    if (i == 0) g_rowptr[N_NODES] = N_EDGES;
}

__global__ void k_fill(const int* __restrict__ edge) {
    int e = blockIdx.x * blockDim.x + threadIdx.x;
    if (e >= N_EDGES) return;
    int s = edge[e];
    int d = edge[N_EDGES + e];
    int p = g_rowptr[d] + atomicAdd(&g_cnt[d], 1);
    g_csr_src[p] = s;
    g_csr_w[p] = g_dinv[s];
}

__global__ void k_agg1(const float* __restrict__ x) {
    int n = blockIdx.x * blockDim.x + threadIdx.x;
    if (n >= N_NODES) return;
    float acc[IN_C];
#pragma unroll
    for (int k = 0; k < IN_C; k++) acc[k] = 0.f;
    int s = g_rowptr[n], e = g_rowptr[n + 1];
    for (int p = s; p < e; p++) {
        int sn = g_csr_src[p];
        float w = g_csr_w[p];
        const float* xr = x + (long)sn * IN_C;
#pragma unroll
        for (int k = 0; k < IN_C; k++) acc[k] += w * xr[k];
    }
    float dn = g_dinv[n];
    float d2 = dn * dn;
    const float* xn = x + (long)n * IN_C;
#pragma unroll
    for (int k = 0; k < IN_C; k++) g_xa[n * IN_C + k] = dn * acc[k] + d2 * xn[k];
}

// h1 = xa @ W1 + b1, fused BN1 stats
#define G1_ROWS 64
__global__ __launch_bounds__(256) void k_gemm1(const float* __restrict__ W1,
                                               const float* __restrict__ b1) {
    __shared__ float W1s[IN_C * HID];
    __shared__ float xas[G1_ROWS * IN_C];
    int t = threadIdx.x;
    int row0 = blockIdx.x * G1_ROWS;
    for (int i = t; i < IN_C * HID; i += 256) W1s[i] = W1[i];
    for (int i = t; i < G1_ROWS * IN_C; i += 256) {
        int r = row0 + i / IN_C;
        xas[i] = (r < N_NODES) ? g_xa[(long)r * IN_C + (i % IN_C)] : 0.f;
    }
    __syncthreads();
    float b1j = b1[t];
    float sum = 0.f, sq = 0.f;
    for (int r = 0; r < G1_ROWS; r++) {
        int row = row0 + r;
        if (row >= N_NODES) break;
        float h = b1j;
#pragma unroll
        for (int k = 0; k < IN_C; k++) h += xas[r * IN_C + k] * W1s[k * HID + t];
        g_h1[(long)row * HID + t] = h;
        sum += h;
        sq += h * h;
    }
    atomicAdd(&g_stat1[t], sum);
    atomicAdd(&g_stat1[HID + t], sq);
}

__global__ void k_bn1(const float* __restrict__ g1, const float* __restrict__ be1) {
    int j = threadIdx.x;
    float mean = g_stat1[j] / (float)N_NODES;
    float var = g_stat1[HID + j] / (float)N_NODES - mean * mean;
    var = fmaxf(var, 0.f);
    float sc = rsqrtf(var + BN_EPS) * g1[j];
    g_sc1[j] = sc;
    g_sh1[j] = be1[j] - mean * sc;
}

// z = relu(bn1(h1)) @ W2, tf32 mma.sync; epilogue writes fp16
#define TCBM 128
#define TCBK 32
#define AS_S 36
#define BS_S 136
__global__ __launch_bounds__(256) void k_gemm2(const float* __restrict__ W2) {
    __shared__ unsigned As[TCBM * AS_S];
    __shared__ unsigned Bs[TCBK * BS_S];
    __shared__ float s1s[HID], t1s[HID];
    const int t = threadIdx.x;
    const int lane = t & 31;
    const int wid = t >> 5;
    const int gid = lane >> 2;
    const int t4 = lane & 3;
    const int warp_row = (wid & 3) * 32;
    const int warp_col = (wid >> 2) * 64;
    const int row0 = blockIdx.x * TCBM;

    for (int i = t; i < HID; i += 256) { s1s[i] = g_sc1[i]; t1s[i] = g_sh1[i]; }

    float acc[2][8][4];
#pragma unroll
    for (int r = 0; r < 2; r++)
#pragma unroll
        for (int c = 0; c < 8; c++)
#pragma unroll
            for (int i = 0; i < 4; i++) acc[r][c][i] = 0.f;
    __syncthreads();

    for (int kt = 0; kt < HID / TCBK; kt++) {
#pragma unroll
        for (int it = 0; it < 4; it++) {
            int q = t + it * 256;
            int row = q >> 3;
            int col4 = (q & 7) * 4;
            int kg = kt * TCBK + col4;
            int grow = row0 + row;
            float4 v = make_float4(0.f, 0.f, 0.f, 0.f);
            if (grow < N_NODES)
                v = *reinterpret_cast<const float4*>(&g_h1[(long)grow * HID + kg]);
            As[row * AS_S + col4 + 0] = f2tf(fmaxf(v.x * s1s[kg + 0] + t1s[kg + 0], 0.f));
            As[row * AS_S + col4 + 1] = f2tf(fmaxf(v.y * s1s[kg + 1] + t1s[kg + 1], 0.f));
            As[row * AS_S + col4 + 2] = f2tf(fmaxf(v.z * s1s[kg + 2] + t1s[kg + 2], 0.f));
            As[row * AS_S + col4 + 3] = f2tf(fmaxf(v.w * s1s[kg + 3] + t1s[kg + 3], 0.f));
        }
#pragma unroll
        for (int it = 0; it < 4; it++) {
            int q = t + it * 256;
            int kb = q >> 5;
            int col4 = (q & 31) * 4;
            float4 v = *reinterpret_cast<const float4*>(&W2[(long)(kt * TCBK + kb) * OUTF + col4]);
            Bs[kb * BS_S + col4 + 0] = f2tf(v.x);
            Bs[kb * BS_S + col4 + 1] = f2tf(v.y);
            Bs[kb * BS_S + col4 + 2] = f2tf(v.z);
            Bs[kb * BS_S + col4 + 3] = f2tf(v.w);
        }
        __syncthreads();
#pragma unroll
        for (int ks = 0; ks < TCBK / 8; ks++) {
            unsigned a[2][4], b[8][2];
#pragma unroll
            for (int r = 0; r < 2; r++) {
                int rb = (warp_row + r * 16 + gid) * AS_S + ks * 8 + t4;
                a[r][0] = As[rb];
                a[r][1] = As[rb + 8 * AS_S];
                a[r][2] = As[rb + 4];
                a[r][3] = As[rb + 8 * AS_S + 4];
            }
#pragma unroll
            for (int c = 0; c < 8; c++) {
                int cb = (ks * 8 + t4) * BS_S + warp_col + c * 8 + gid;
                b[c][0] = Bs[cb];
                b[c][1] = Bs[cb + 4 * BS_S];
            }
#pragma unroll
            for (int r = 0; r < 2; r++)
#pragma unroll
                for (int c = 0; c < 8; c++) mma_tf32(acc[r][c], a[r], b[c]);
        }
        __syncthreads();
    }
#pragma unroll
    for (int r = 0; r < 2; r++) {
        int rowA = row0 + warp_row + r * 16 + gid;
        int rowB = rowA + 8;
#pragma unroll
        for (int c = 0; c < 8; c++) {
            int col = warp_col + c * 8 + t4 * 2;
            if (rowA < N_NODES)
                *reinterpret_cast<__half2*>(&g_zh[(long)rowA * OUTF + col]) =
                    __floats2half2_rn(acc[r][c][0], acc[r][c][1]);
            if (rowB < N_NODES)
                *reinterpret_cast<__half2*>(&g_zh[(long)rowB * OUTF + col]) =
                    __floats2half2_rn(acc[r][c][2], acc[r][c][3]);
        }
    }
}

// agg2: thread-per-column, 8 nodes/block, 4-edge batch; fp16 z gathers
#define A2_NPB 8
__global__ __launch_bounds__(128) void k_agg2(const float* __restrict__ b2) {
    int j = threadIdx.x;
    int n0 = blockIdx.x * A2_NPB;
    float b2j = b2[j];
    float bs = 0.f, bq = 0.f;
#pragma unroll 1
    for (int u = 0; u < A2_NPB; u++) {
        int n = n0 + u;
        int s = g_rowptr[n], e = g_rowptr[n + 1];
        float acc = 0.f;
        int p = s;
        for (; p + 4 <= e; p += 4) {
            int s0 = g_csr_src[p + 0], s1 = g_csr_src[p + 1];
            int s2 = g_csr_src[p + 2], s3 = g_csr_src[p + 3];
            float w0 = g_csr_w[p + 0], w1 = g_csr_w[p + 1];
            float w2 = g_csr_w[p + 2], w3 = g_csr_w[p + 3];
            float z0 = __half2float(g_zh[(long)s0 * OUTF + j]);
            float z1 = __half2float(g_zh[(long)s1 * OUTF + j]);
            float z2 = __half2float(g_zh[(long)s2 * OUTF + j]);
            float z3 = __half2float(g_zh[(long)s3 * OUTF + j]);
            acc += w0 * z0 + w1 * z1 + w2 * z2 + w3 * z3;
        }
        for (; p < e; p++)
            acc += g_csr_w[p] * __half2float(g_zh[(long)g_csr_src[p] * OUTF + j]);
        float dn = g_dinv[n];
        float val = dn * acc + dn * dn * __half2float(g_zh[(long)n * OUTF + j]) + b2j;
        g_h2[(long)n * OUTF + j] = val;
        bs += val;
        bq += val * val;
    }
    atomicAdd(&g_stat2[j], bs);
    atomicAdd(&g_stat2[OUTF + j], bq);
}

__global__ void k_bn2(const float* __restrict__ g2, const float* __restrict__ be2) {
    int j = threadIdx.x;
    float mean = g_stat2[j] / (float)N_NODES;
    float var = g_stat2[OUTF + j] / (float)N_NODES - mean * mean;
    var = fmaxf(var, 0.f);
    float sc = rsqrtf(var + BN_EPS) * g2[j];
    g_sc2[j] = sc;
    g_sh2[j] = be2[j] - mean * sc;
}

__global__ void k_gstart(const int* __restrict__ batch) {
    int i = blockIdx.x * blockDim.x + threadIdx.x;
    if (i > N_NODES) return;
    int b = (i < N_NODES) ? batch[i] : N_GRAPHS;
    int bp = (i > 0) ? batch[i - 1] : -1;
    for (int g = bp + 1; g <= b && g <= N_GRAPHS; g++) g_gstart[g] = i;
}

__global__ __launch_bounds__(128) void k_pool(float* __restrict__ out) {
    int g = blockIdx.x;
    int j = threadIdx.x;
    int s = g_gstart[g], e = g_gstart[g + 1];
    float acc = 0.f;
    for (int i = s; i < e; i++) acc += g_h2[(long)i * OUTF + j];
    int cnt = e - s;
    float y = 0.f;
    if (cnt > 0) {
        float p = acc / (float)cnt;
        y = p * g_sc2[j] + g_sh2[j];
    }
    float v = y * y;
#pragma unroll
    for (int off = 16; off > 0; off >>= 1) v += __shfl_xor_sync(0xffffffffu, v, off);
    __shared__ float ws[4];
    if ((j & 31) == 0) ws[j >> 5] = v;
    __syncthreads();
    float ss = ws[0] + ws[1] + ws[2] + ws[3];
    float nrm = sqrtf(ss);
    out[g * OUTF + j] = y / fmaxf(nrm, 1e-12f);
}

// ---------------- launch ----------------
extern "C" void kernel_launch(void* const* d_in, const int* in_sizes, int n_in,
                              void* d_out, int out_size) {
    const float* x   = (const float*)d_in[0];
    const float* W1  = (const float*)d_in[1];
    const float* b1  = (const float*)d_in[2];
    const float* g1  = (const float*)d_in[3];
    const float* be1 = (const float*)d_in[4];
    const float* W2  = (const float*)d_in[5];
    const float* b2  = (const float*)d_in[6];
    const float* g2  = (const float*)d_in[7];
    const float* be2 = (const float*)d_in[8];
    const int* edge  = (const int*)d_in[9];
    const int* batch = (const int*)d_in[10];
    float* out = (float*)d_out;

    const int TB = 256;
    int nb_N = (N_NODES + TB - 1) / TB;
    int nb_E = (N_EDGES + TB - 1) / TB;

    k_init<<<nb_N, TB>>>();
    k_count<<<nb_E, TB>>>(edge);
    k_scan1<<<SCAN_NB, SCAN_B>>>();
    k_scan2<<<1, 128>>>();
    k_scan3<<<SCAN_NB, SCAN_B>>>();
    k_fill<<<nb_E, TB>>>(edge);
    k_agg1<<<nb_N, TB>>>(x);
    k_gemm1<<<(N_NODES + G1_ROWS - 1) / G1_ROWS, 256>>>(W1, b1);
    k_bn1<<<1, HID>>>(g1, be1);
    k_gemm2<<<(N_NODES + TCBM - 1) / TCBM, 256>>>(W2);
    k_agg2<<<N_NODES / A2_NPB, 128>>>(b2);
    k_bn2<<<1, OUTF>>>(g2, be2);
    k_gstart<<<(N_NODES + 1 + TB - 1) / TB, TB>>>(batch);
    k_pool<<<N_GRAPHS, 128>>>(out);
}

// round 11
// speedup vs baseline: 2.1357x; 1.0520x over previous
#include <cuda_runtime.h>
#include <cuda_fp16.h>
#include <math.h>

#define N_NODES 100000
#define N_EDGES 1600000
#define N_GRAPHS 2000
#define IN_C 9
#define HID 256
#define OUTF 128
#define BN_EPS 1e-5f

#define SCAN_B 1024
#define SCAN_NB ((N_NODES + SCAN_B - 1) / SCAN_B)   // 98

// ---------------- scratch ----------------
__device__ float g_dinv[N_NODES];
__device__ int   g_cnt[N_NODES];          // counts -> fill cursors (seeded to rowptr)
__device__ int   g_rowptr[N_NODES + 1];
__device__ int   g_bsum[SCAN_NB];
__device__ int   g_csr_src[N_EDGES];
__device__ float g_xp[N_NODES * IN_C];    // x prescaled by dinv
__device__ float g_xa[N_NODES * IN_C];
__device__ __align__(16) float  g_h1[N_NODES * HID];
__device__ __align__(16) __half g_zh[N_NODES * OUTF];   // z' = dinv*z, fp16
__device__ __align__(16) float  g_h2[N_NODES * OUTF];
__device__ float g_stat1[2 * HID];
__device__ float g_stat2[2 * OUTF];
__device__ float g_sc1[HID], g_sh1[HID];
__device__ float g_sc2[OUTF], g_sh2[OUTF];
__device__ int   g_gstart[N_GRAPHS + 1];

// ---------------- helpers ----------------
__device__ __forceinline__ unsigned f2tf(float f) {
    unsigned r;
    asm("cvt.rna.tf32.f32 %0, %1;" : "=r"(r) : "f"(f));
    return r;
}
__device__ __forceinline__ void mma_tf32(float* d, const unsigned* a, const unsigned* b) {
    asm volatile(
        "mma.sync.aligned.m16n8k8.row.col.f32.tf32.tf32.f32 "
        "{%0,%1,%2,%3}, {%4,%5,%6,%7}, {%8,%9}, {%0,%1,%2,%3};"
        : "+f"(d[0]), "+f"(d[1]), "+f"(d[2]), "+f"(d[3])
        : "r"(a[0]), "r"(a[1]), "r"(a[2]), "r"(a[3]), "r"(b[0]), "r"(b[1]));
}

// ---------------- kernels ----------------

__global__ void k_init() {
    int i = blockIdx.x * blockDim.x + threadIdx.x;
    if (i < N_NODES) g_cnt[i] = 0;
    if (i < 2 * HID) g_stat1[i] = 0.f;
    if (i < 2 * OUTF) g_stat2[i] = 0.f;
}

__global__ void k_count(const int* __restrict__ edge) {
    int e = blockIdx.x * blockDim.x + threadIdx.x;
    if (e >= N_EDGES) return;
    atomicAdd(&g_cnt[edge[N_EDGES + e]], 1);
}

__global__ __launch_bounds__(SCAN_B) void k_scan1() {
    __shared__ int sh[SCAN_B];
    int t = threadIdx.x;
    int i = blockIdx.x * SCAN_B + t;
    int c = (i < N_NODES) ? g_cnt[i] : 0;
    if (i < N_NODES) g_dinv[i] = rsqrtf((float)(c + 1));
    sh[t] = c;
    __syncthreads();
#pragma unroll
    for (int off = 1; off < SCAN_B; off <<= 1) {
        int v = sh[t];
        int add = (t >= off) ? sh[t - off] : 0;
        __syncthreads();
        sh[t] = v + add;
        __syncthreads();
    }
    if (i < N_NODES) g_rowptr[i] = sh[t] - c;
    if (t == SCAN_B - 1) g_bsum[blockIdx.x] = sh[t];
}

__global__ void k_scan2() {
    __shared__ int sh[128];
    int t = threadIdx.x;
    int v = (t < SCAN_NB) ? g_bsum[t] : 0;
    sh[t] = v;
    __syncthreads();
#pragma unroll
    for (int off = 1; off < 128; off <<= 1) {
        int x = sh[t];
        int add = (t >= off) ? sh[t - off] : 0;
        __syncthreads();
        sh[t] = x + add;
        __syncthreads();
    }
    if (t < SCAN_NB) g_bsum[t] = sh[t] - v;
}

// add block offsets; seed fill cursors with rowptr; write prescaled x'
__global__ __launch_bounds__(SCAN_B) void k_scan3(const float* __restrict__ x) {
    int i = blockIdx.x * SCAN_B + threadIdx.x;
    if (i < N_NODES) {
        int rp = g_rowptr[i] + g_bsum[blockIdx.x];
        g_rowptr[i] = rp;
        g_cnt[i] = rp;                      // fill cursor base
        float dn = g_dinv[i];
        const float* xr = x + (long)i * IN_C;
        float* xw = g_xp + (long)i * IN_C;
#pragma unroll
        for (int k = 0; k < IN_C; k++) xw[k] = dn * xr[k];
    }
    if (i == 0) g_rowptr[N_NODES] = N_EDGES;
}

// fill: single atomic cursor, one scattered 4B write per edge
__global__ void k_fill(const int* __restrict__ edge) {
    int e = blockIdx.x * blockDim.x + threadIdx.x;
    if (e >= N_EDGES) return;
    int s = edge[e];
    int d = edge[N_EDGES + e];
    int p = atomicAdd(&g_cnt[d], 1);
    g_csr_src[p] = s;
}

// xa[n] = dinv[n] * (sum_{sn} x'[sn] + x'[n])
__global__ void k_agg1() {
    int n = blockIdx.x * blockDim.x + threadIdx.x;
    if (n >= N_NODES) return;
    float acc[IN_C];
    const float* xn = g_xp + (long)n * IN_C;
#pragma unroll
    for (int k = 0; k < IN_C; k++) acc[k] = xn[k];
    int s = g_rowptr[n], e = g_rowptr[n + 1];
    for (int p = s; p < e; p++) {
        int sn = g_csr_src[p];
        const float* xr = g_xp + (long)sn * IN_C;
#pragma unroll
        for (int k = 0; k < IN_C; k++) acc[k] += xr[k];
    }
    float dn = g_dinv[n];
#pragma unroll
    for (int k = 0; k < IN_C; k++) g_xa[n * IN_C + k] = dn * acc[k];
}

// h1 = xa @ W1 + b1, fused BN1 stats
#define G1_ROWS 64
__global__ __launch_bounds__(256) void k_gemm1(const float* __restrict__ W1,
                                               const float* __restrict__ b1) {
    __shared__ float W1s[IN_C * HID];
    __shared__ float xas[G1_ROWS * IN_C];
    int t = threadIdx.x;
    int row0 = blockIdx.x * G1_ROWS;
    for (int i = t; i < IN_C * HID; i += 256) W1s[i] = W1[i];
    for (int i = t; i < G1_ROWS * IN_C; i += 256) {
        int r = row0 + i / IN_C;
        xas[i] = (r < N_NODES) ? g_xa[(long)r * IN_C + (i % IN_C)] : 0.f;
    }
    __syncthreads();
    float b1j = b1[t];
    float sum = 0.f, sq = 0.f;
    for (int r = 0; r < G1_ROWS; r++) {
        int row = row0 + r;
        if (row >= N_NODES) break;
        float h = b1j;
#pragma unroll
        for (int k = 0; k < IN_C; k++) h += xas[r * IN_C + k] * W1s[k * HID + t];
        g_h1[(long)row * HID + t] = h;
        sum += h;
        sq += h * h;
    }
    atomicAdd(&g_stat1[t], sum);
    atomicAdd(&g_stat1[HID + t], sq);
}

__global__ void k_bn1(const float* __restrict__ g1, const float* __restrict__ be1) {
    int j = threadIdx.x;
    float mean = g_stat1[j] / (float)N_NODES;
    float var = g_stat1[HID + j] / (float)N_NODES - mean * mean;
    var = fmaxf(var, 0.f);
    float sc = rsqrtf(var + BN_EPS) * g1[j];
    g_sc1[j] = sc;
    g_sh1[j] = be1[j] - mean * sc;
}

// z' = dinv * (relu(bn1(h1)) @ W2), tf32 mma; epilogue scales by dinv, writes fp16
#define TCBM 128
#define TCBK 32
#define AS_S 36
#define BS_S 136
__global__ __launch_bounds__(256) void k_gemm2(const float* __restrict__ W2) {
    __shared__ unsigned As[TCBM * AS_S];
    __shared__ unsigned Bs[TCBK * BS_S];
    __shared__ float s1s[HID], t1s[HID];
    const int t = threadIdx.x;
    const int lane = t & 31;
    const int wid = t >> 5;
    const int gid = lane >> 2;
    const int t4 = lane & 3;
    const int warp_row = (wid & 3) * 32;
    const int warp_col = (wid >> 2) * 64;
    const int row0 = blockIdx.x * TCBM;

    for (int i = t; i < HID; i += 256) { s1s[i] = g_sc1[i]; t1s[i] = g_sh1[i]; }

    float acc[2][8][4];
#pragma unroll
    for (int r = 0; r < 2; r++)
#pragma unroll
        for (int c = 0; c < 8; c++)
#pragma unroll
            for (int i = 0; i < 4; i++) acc[r][c][i] = 0.f;
    __syncthreads();

    for (int kt = 0; kt < HID / TCBK; kt++) {
#pragma unroll
        for (int it = 0; it < 4; it++) {
            int q = t + it * 256;
            int row = q >> 3;
            int col4 = (q & 7) * 4;
            int kg = kt * TCBK + col4;
            int grow = row0 + row;
            float4 v = make_float4(0.f, 0.f, 0.f, 0.f);
            if (grow < N_NODES)
                v = *reinterpret_cast<const float4*>(&g_h1[(long)grow * HID + kg]);
            As[row * AS_S + col4 + 0] = f2tf(fmaxf(v.x * s1s[kg + 0] + t1s[kg + 0], 0.f));
            As[row * AS_S + col4 + 1] = f2tf(fmaxf(v.y * s1s[kg + 1] + t1s[kg + 1], 0.f));
            As[row * AS_S + col4 + 2] = f2tf(fmaxf(v.z * s1s[kg + 2] + t1s[kg + 2], 0.f));
            As[row * AS_S + col4 + 3] = f2tf(fmaxf(v.w * s1s[kg + 3] + t1s[kg + 3], 0.f));
        }
#pragma unroll
        for (int it = 0; it < 4; it++) {
            int q = t + it * 256;
            int kb = q >> 5;
            int col4 = (q & 31) * 4;
            float4 v = *reinterpret_cast<const float4*>(&W2[(long)(kt * TCBK + kb) * OUTF + col4]);
            Bs[kb * BS_S + col4 + 0] = f2tf(v.x);
            Bs[kb * BS_S + col4 + 1] = f2tf(v.y);
            Bs[kb * BS_S + col4 + 2] = f2tf(v.z);
            Bs[kb * BS_S + col4 + 3] = f2tf(v.w);
        }
        __syncthreads();
#pragma unroll
        for (int ks = 0; ks < TCBK / 8; ks++) {
            unsigned a[2][4], b[8][2];
#pragma unroll
            for (int r = 0; r < 2; r++) {
                int rb = (warp_row + r * 16 + gid) * AS_S + ks * 8 + t4;
                a[r][0] = As[rb];
                a[r][1] = As[rb + 8 * AS_S];
                a[r][2] = As[rb + 4];
                a[r][3] = As[rb + 8 * AS_S + 4];
            }
#pragma unroll
            for (int c = 0; c < 8; c++) {
                int cb = (ks * 8 + t4) * BS_S + warp_col + c * 8 + gid;
                b[c][0] = Bs[cb];
                b[c][1] = Bs[cb + 4 * BS_S];
            }
#pragma unroll
            for (int r = 0; r < 2; r++)
#pragma unroll
                for (int c = 0; c < 8; c++) mma_tf32(acc[r][c], a[r], b[c]);
        }
        __syncthreads();
    }
#pragma unroll
    for (int r = 0; r < 2; r++) {
        int rowA = row0 + warp_row + r * 16 + gid;
        int rowB = rowA + 8;
        float dA = (rowA < N_NODES) ? g_dinv[rowA] : 0.f;
        float dB = (rowB < N_NODES) ? g_dinv[rowB] : 0.f;
#pragma unroll
        for (int c = 0; c < 8; c++) {
            int col = warp_col + c * 8 + t4 * 2;
            if (rowA < N_NODES)
                *reinterpret_cast<__half2*>(&g_zh[(long)rowA * OUTF + col]) =
                    __floats2half2_rn(dA * acc[r][c][0], dA * acc[r][c][1]);
            if (rowB < N_NODES)
                *reinterpret_cast<__half2*>(&g_zh[(long)rowB * OUTF + col]) =
                    __floats2half2_rn(dB * acc[r][c][2], dB * acc[r][c][3]);
        }
    }
}

// agg2: h2[n] = dinv[n]*(sum z'[sn] + z'[n]) + b2; fused BN2 stats
#define A2_NPB 8
__global__ __launch_bounds__(128) void k_agg2(const float* __restrict__ b2) {
    int j = threadIdx.x;
    int n0 = blockIdx.x * A2_NPB;
    float b2j = b2[j];
    float bs = 0.f, bq = 0.f;
#pragma unroll 1
    for (int u = 0; u < A2_NPB; u++) {
        int n = n0 + u;
        int s = g_rowptr[n], e = g_rowptr[n + 1];
        float acc = __half2float(g_zh[(long)n * OUTF + j]);   // self-loop term
        int p = s;
        for (; p + 4 <= e; p += 4) {
            int s0 = g_csr_src[p + 0], s1 = g_csr_src[p + 1];
            int s2 = g_csr_src[p + 2], s3 = g_csr_src[p + 3];
            float z0 = __half2float(g_zh[(long)s0 * OUTF + j]);
            float z1 = __half2float(g_zh[(long)s1 * OUTF + j]);
            float z2 = __half2float(g_zh[(long)s2 * OUTF + j]);
            float z3 = __half2float(g_zh[(long)s3 * OUTF + j]);
            acc += z0 + z1 + z2 + z3;
        }
        for (; p < e; p++)
            acc += __half2float(g_zh[(long)g_csr_src[p] * OUTF + j]);
        float dn = g_dinv[n];
        float val = dn * acc + b2j;
        g_h2[(long)n * OUTF + j] = val;
        bs += val;
        bq += val * val;
    }
    atomicAdd(&g_stat2[j], bs);
    atomicAdd(&g_stat2[OUTF + j], bq);
}

__global__ void k_bn2(const float* __restrict__ g2, const float* __restrict__ be2) {
    int j = threadIdx.x;
    float mean = g_stat2[j] / (float)N_NODES;
    float var = g_stat2[OUTF + j] / (float)N_NODES - mean * mean;
    var = fmaxf(var, 0.f);
    float sc = rsqrtf(var + BN_EPS) * g2[j];
    g_sc2[j] = sc;
    g_sh2[j] = be2[j] - mean * sc;
}

__global__ void k_gstart(const int* __restrict__ batch) {
    int i = blockIdx.x * blockDim.x + threadIdx.x;
    if (i > N_NODES) return;
    int b = (i < N_NODES) ? batch[i] : N_GRAPHS;
    int bp = (i > 0) ? batch[i - 1] : -1;
    for (int g = bp + 1; g <= b && g <= N_GRAPHS; g++) g_gstart[g] = i;
}

__global__ __launch_bounds__(128) void k_pool(float* __restrict__ out) {
    int g = blockIdx.x;
    int j = threadIdx.x;
    int s = g_gstart[g], e = g_gstart[g + 1];
    float acc = 0.f;
    for (int i = s; i < e; i++) acc += g_h2[(long)i * OUTF + j];
    int cnt = e - s;
    float y = 0.f;
    if (cnt > 0) {
        float p = acc / (float)cnt;
        y = p * g_sc2[j] + g_sh2[j];
    }
    float v = y * y;
#pragma unroll
    for (int off = 16; off > 0; off >>= 1) v += __shfl_xor_sync(0xffffffffu, v, off);
    __shared__ float ws[4];
    if ((j & 31) == 0) ws[j >> 5] = v;
    __syncthreads();
    float ss = ws[0] + ws[1] + ws[2] + ws[3];
    float nrm = sqrtf(ss);
    out[g * OUTF + j] = y / fmaxf(nrm, 1e-12f);
}

// ---------------- launch ----------------
extern "C" void kernel_launch(void* const* d_in, const int* in_sizes, int n_in,
                              void* d_out, int out_size) {
    const float* x   = (const float*)d_in[0];
    const float* W1  = (const float*)d_in[1];
    const float* b1  = (const float*)d_in[2];
    const float* g1  = (const float*)d_in[3];
    const float* be1 = (const float*)d_in[4];
    const float* W2  = (const float*)d_in[5];
    const float* b2  = (const float*)d_in[6];
    const float* g2  = (const float*)d_in[7];
    const float* be2 = (const float*)d_in[8];
    const int* edge  = (const int*)d_in[9];
    const int* batch = (const int*)d_in[10];
    float* out = (float*)d_out;

    const int TB = 256;
    int nb_N = (N_NODES + TB - 1) / TB;
    int nb_E = (N_EDGES + TB - 1) / TB;

    k_init<<<nb_N, TB>>>();
    k_count<<<nb_E, TB>>>(edge);
    k_scan1<<<SCAN_NB, SCAN_B>>>();
    k_scan2<<<1, 128>>>();
    k_scan3<<<SCAN_NB, SCAN_B>>>(x);
    k_fill<<<nb_E, TB>>>(edge);
    k_agg1<<<nb_N, TB>>>();
    k_gemm1<<<(N_NODES + G1_ROWS - 1) / G1_ROWS, 256>>>(W1, b1);
    k_bn1<<<1, HID>>>(g1, be1);
    k_gemm2<<<(N_NODES + TCBM - 1) / TCBM, 256>>>(W2);
    k_agg2<<<N_NODES / A2_NPB, 128>>>(b2);
    k_bn2<<<1, OUTF>>>(g2, be2);
    k_gstart<<<(N_NODES + 1 + TB - 1) / TB, TB>>>(batch);
    k_pool<<<N_GRAPHS, 128>>>(out);
}

// round 12
// speedup vs baseline: 2.2064x; 1.0331x over previous
#include <cuda_runtime.h>
#include <cuda_fp16.h>
#include <math.h>

#define N_NODES 100000
#define N_EDGES 1600000
#define N_GRAPHS 2000
#define IN_C 9
#define HID 256
#define OUTF 128
#define BN_EPS 1e-5f

#define SCAN_B 1024
#define SCAN_NB ((N_NODES + SCAN_B - 1) / SCAN_B)   // 98

// ---------------- scratch ----------------
__device__ float g_dinv[N_NODES];
__device__ int   g_cnt[N_NODES];          // counts -> fill cursors
__device__ int   g_rowptr[N_NODES + 1];
__device__ int   g_bsum[SCAN_NB];
__device__ int   g_csr_src[N_EDGES];
__device__ float g_xp[N_NODES * IN_C];    // x prescaled by dinv
__device__ float g_xa[N_NODES * IN_C];
__device__ __align__(16) __half g_h1h[N_NODES * HID];  // raw pre-BN h1, fp16
__device__ __align__(16) __half g_zh [N_NODES * OUTF]; // z' = dinv*z, fp16
__device__ __align__(16) float  g_h2[N_NODES * OUTF];
__device__ float g_stat1[2 * HID];
__device__ float g_stat2[2 * OUTF];
__device__ int   g_gstart[N_GRAPHS + 1];

// ---------------- helpers ----------------
__device__ __forceinline__ unsigned f2tf(float f) {
    unsigned r;
    asm("cvt.rna.tf32.f32 %0, %1;" : "=r"(r) : "f"(f));
    return r;
}
__device__ __forceinline__ void mma_tf32(float* d, const unsigned* a, const unsigned* b) {
    asm volatile(
        "mma.sync.aligned.m16n8k8.row.col.f32.tf32.tf32.f32 "
        "{%0,%1,%2,%3}, {%4,%5,%6,%7}, {%8,%9}, {%0,%1,%2,%3};"
        : "+f"(d[0]), "+f"(d[1]), "+f"(d[2]), "+f"(d[3])
        : "r"(a[0]), "r"(a[1]), "r"(a[2]), "r"(a[3]), "r"(b[0]), "r"(b[1]));
}

// ---------------- kernels ----------------

__global__ void k_init() {
    int i = blockIdx.x * blockDim.x + threadIdx.x;
    if (i < N_NODES) g_cnt[i] = 0;
    if (i < 2 * HID) g_stat1[i] = 0.f;
    if (i < 2 * OUTF) g_stat2[i] = 0.f;
}

__global__ void k_count(const int* __restrict__ edge) {
    int e = blockIdx.x * blockDim.x + threadIdx.x;
    if (e >= N_EDGES) return;
    atomicAdd(&g_cnt[edge[N_EDGES + e]], 1);
}

__global__ __launch_bounds__(SCAN_B) void k_scan1() {
    __shared__ int sh[SCAN_B];
    int t = threadIdx.x;
    int i = blockIdx.x * SCAN_B + t;
    int c = (i < N_NODES) ? g_cnt[i] : 0;
    if (i < N_NODES) g_dinv[i] = rsqrtf((float)(c + 1));
    sh[t] = c;
    __syncthreads();
#pragma unroll
    for (int off = 1; off < SCAN_B; off <<= 1) {
        int v = sh[t];
        int add = (t >= off) ? sh[t - off] : 0;
        __syncthreads();
        sh[t] = v + add;
        __syncthreads();
    }
    if (i < N_NODES) g_rowptr[i] = sh[t] - c;
    if (t == SCAN_B - 1) g_bsum[blockIdx.x] = sh[t];
}

__global__ void k_scan2() {
    __shared__ int sh[128];
    int t = threadIdx.x;
    int v = (t < SCAN_NB) ? g_bsum[t] : 0;
    sh[t] = v;
    __syncthreads();
#pragma unroll
    for (int off = 1; off < 128; off <<= 1) {
        int x = sh[t];
        int add = (t >= off) ? sh[t - off] : 0;
        __syncthreads();
        sh[t] = x + add;
        __syncthreads();
    }
    if (t < SCAN_NB) g_bsum[t] = sh[t] - v;
}

// add block offsets; seed fill cursors; write prescaled x'
__global__ __launch_bounds__(SCAN_B) void k_scan3(const float* __restrict__ x) {
    int i = blockIdx.x * SCAN_B + threadIdx.x;
    if (i < N_NODES) {
        int rp = g_rowptr[i] + g_bsum[blockIdx.x];
        g_rowptr[i] = rp;
        g_cnt[i] = rp;
        float dn = g_dinv[i];
        const float* xr = x + (long)i * IN_C;
        float* xw = g_xp + (long)i * IN_C;
#pragma unroll
        for (int k = 0; k < IN_C; k++) xw[k] = dn * xr[k];
    }
    if (i == 0) g_rowptr[N_NODES] = N_EDGES;
}

// fill CSR (single atomic cursor + scattered 4B write); fused gstart
__global__ void k_fill(const int* __restrict__ edge, const int* __restrict__ batch) {
    int e = blockIdx.x * blockDim.x + threadIdx.x;
    if (e < N_EDGES) {
        int s = edge[e];
        int d = edge[N_EDGES + e];
        int p = atomicAdd(&g_cnt[d], 1);
        g_csr_src[p] = s;
    }
    if (e <= N_NODES) {
        int b = (e < N_NODES) ? batch[e] : N_GRAPHS;
        int bp = (e > 0) ? batch[e - 1] : -1;
        for (int g = bp + 1; g <= b && g <= N_GRAPHS; g++) g_gstart[g] = e;
    }
}

// xa[n] = dinv[n] * (sum_{sn} x'[sn] + x'[n])
__global__ void k_agg1() {
    int n = blockIdx.x * blockDim.x + threadIdx.x;
    if (n >= N_NODES) return;
    float acc[IN_C];
    const float* xn = g_xp + (long)n * IN_C;
#pragma unroll
    for (int k = 0; k < IN_C; k++) acc[k] = xn[k];
    int s = g_rowptr[n], e = g_rowptr[n + 1];
    for (int p = s; p < e; p++) {
        int sn = g_csr_src[p];
        const float* xr = g_xp + (long)sn * IN_C;
#pragma unroll
        for (int k = 0; k < IN_C; k++) acc[k] += xr[k];
    }
    float dn = g_dinv[n];
#pragma unroll
    for (int k = 0; k < IN_C; k++) g_xa[n * IN_C + k] = dn * acc[k];
}

// h1 = xa @ W1 + b1 (stored raw fp16), fused BN1 stats. 256 rows/block.
#define G1_ROWS 256
__global__ __launch_bounds__(256) void k_gemm1(const float* __restrict__ W1,
                                               const float* __restrict__ b1) {
    __shared__ float W1s[IN_C * HID];
    __shared__ float xas[G1_ROWS * IN_C];
    int t = threadIdx.x;
    int row0 = blockIdx.x * G1_ROWS;
    for (int i = t; i < IN_C * HID; i += 256) W1s[i] = W1[i];
    for (int i = t; i < G1_ROWS * IN_C; i += 256) {
        int r = row0 + i / IN_C;
        xas[i] = (r < N_NODES) ? g_xa[(long)r * IN_C + (i % IN_C)] : 0.f;
    }
    __syncthreads();
    float b1j = b1[t];
    float w[IN_C];
#pragma unroll
    for (int k = 0; k < IN_C; k++) w[k] = W1s[k * HID + t];
    float sum = 0.f, sq = 0.f;
    for (int r = 0; r < G1_ROWS; r++) {
        int row = row0 + r;
        if (row >= N_NODES) break;
        float h0 = b1j, h1 = 0.f, h2 = 0.f;
#pragma unroll
        for (int k = 0; k < IN_C; k += 3) {
            h0 += xas[r * IN_C + k] * w[k];
            if (k + 1 < IN_C) h1 += xas[r * IN_C + k + 1] * w[k + 1];
            if (k + 2 < IN_C) h2 += xas[r * IN_C + k + 2] * w[k + 2];
        }
        float h = h0 + h1 + h2;
        g_h1h[(long)row * HID + t] = __float2half(h);
        sum += h;
        sq += h * h;
    }
    atomicAdd(&g_stat1[t], sum);
    atomicAdd(&g_stat1[HID + t], sq);
}

// z' = dinv * (relu(bn1(h1)) @ W2); BN1 affine computed in prologue from stats
#define TCBM 128
#define TCBK 32
#define AS_S 36
#define BS_S 136
__global__ __launch_bounds__(256) void k_gemm2(const float* __restrict__ W2,
                                               const float* __restrict__ g1,
                                               const float* __restrict__ be1) {
    __shared__ unsigned As[TCBM * AS_S];
    __shared__ unsigned Bs[TCBK * BS_S];
    __shared__ float s1s[HID], t1s[HID];
    const int t = threadIdx.x;
    const int lane = t & 31;
    const int wid = t >> 5;
    const int gid = lane >> 2;
    const int t4 = lane & 3;
    const int warp_row = (wid & 3) * 32;
    const int warp_col = (wid >> 2) * 64;
    const int row0 = blockIdx.x * TCBM;

    // BN1 affine from raw stats (each block redundantly; 256 threads = 256 cols)
    {
        float mean = g_stat1[t] / (float)N_NODES;
        float var = g_stat1[HID + t] / (float)N_NODES - mean * mean;
        var = fmaxf(var, 0.f);
        float sc = rsqrtf(var + BN_EPS) * g1[t];
        s1s[t] = sc;
        t1s[t] = be1[t] - mean * sc;
    }

    float acc[2][8][4];
#pragma unroll
    for (int r = 0; r < 2; r++)
#pragma unroll
        for (int c = 0; c < 8; c++)
#pragma unroll
            for (int i = 0; i < 4; i++) acc[r][c][i] = 0.f;
    __syncthreads();

    for (int kt = 0; kt < HID / TCBK; kt++) {
        // A chunk: 128 rows x 32 cols from fp16 h1; BN+relu in fp32; tf32
#pragma unroll
        for (int it = 0; it < 2; it++) {
            int q = t + it * 256;
            int row = q >> 2;
            int col8 = (q & 3) * 8;
            int kg = kt * TCBK + col8;
            int grow = row0 + row;
            uint4 raw = make_uint4(0u, 0u, 0u, 0u);
            if (grow < N_NODES)
                raw = *reinterpret_cast<const uint4*>(&g_h1h[(long)grow * HID + kg]);
            const __half2* hp = reinterpret_cast<const __half2*>(&raw);
#pragma unroll
            for (int u = 0; u < 4; u++) {
                float2 f = __half22float2(hp[u]);
                int k0 = kg + u * 2;
                As[row * AS_S + col8 + u * 2 + 0] =
                    f2tf(fmaxf(f.x * s1s[k0 + 0] + t1s[k0 + 0], 0.f));
                As[row * AS_S + col8 + u * 2 + 1] =
                    f2tf(fmaxf(f.y * s1s[k0 + 1] + t1s[k0 + 1], 0.f));
            }
        }
        // B chunk
#pragma unroll
        for (int it = 0; it < 4; it++) {
            int q = t + it * 256;
            int kb = q >> 5;
            int col4 = (q & 31) * 4;
            float4 v = *reinterpret_cast<const float4*>(&W2[(long)(kt * TCBK + kb) * OUTF + col4]);
            Bs[kb * BS_S + col4 + 0] = f2tf(v.x);
            Bs[kb * BS_S + col4 + 1] = f2tf(v.y);
            Bs[kb * BS_S + col4 + 2] = f2tf(v.z);
            Bs[kb * BS_S + col4 + 3] = f2tf(v.w);
        }
        __syncthreads();
#pragma unroll
        for (int ks = 0; ks < TCBK / 8; ks++) {
            unsigned a[2][4], b[8][2];
#pragma unroll
            for (int r = 0; r < 2; r++) {
                int rb = (warp_row + r * 16 + gid) * AS_S + ks * 8 + t4;
                a[r][0] = As[rb];
                a[r][1] = As[rb + 8 * AS_S];
                a[r][2] = As[rb + 4];
                a[r][3] = As[rb + 8 * AS_S + 4];
            }
#pragma unroll
            for (int c = 0; c < 8; c++) {
                int cb = (ks * 8 + t4) * BS_S + warp_col + c * 8 + gid;
                b[c][0] = Bs[cb];
                b[c][1] = Bs[cb + 4 * BS_S];
            }
#pragma unroll
            for (int r = 0; r < 2; r++)
#pragma unroll
                for (int c = 0; c < 8; c++) mma_tf32(acc[r][c], a[r], b[c]);
        }
        __syncthreads();
    }
#pragma unroll
    for (int r = 0; r < 2; r++) {
        int rowA = row0 + warp_row + r * 16 + gid;
        int rowB = rowA + 8;
        float dA = (rowA < N_NODES) ? g_dinv[rowA] : 0.f;
        float dB = (rowB < N_NODES) ? g_dinv[rowB] : 0.f;
#pragma unroll
        for (int c = 0; c < 8; c++) {
            int col = warp_col + c * 8 + t4 * 2;
            if (rowA < N_NODES)
                *reinterpret_cast<__half2*>(&g_zh[(long)rowA * OUTF + col]) =
                    __floats2half2_rn(dA * acc[r][c][0], dA * acc[r][c][1]);
            if (rowB < N_NODES)
                *reinterpret_cast<__half2*>(&g_zh[(long)rowB * OUTF + col]) =
                    __floats2half2_rn(dB * acc[r][c][2], dB * acc[r][c][3]);
        }
    }
}

// agg2: h2[n] = dinv[n]*(sum z'[sn] + z'[n]) + b2; fused BN2 stats
#define A2_NPB 8
__global__ __launch_bounds__(128) void k_agg2(const float* __restrict__ b2) {
    int j = threadIdx.x;
    int n0 = blockIdx.x * A2_NPB;
    float b2j = b2[j];
    float bs = 0.f, bq = 0.f;
#pragma unroll 1
    for (int u = 0; u < A2_NPB; u++) {
        int n = n0 + u;
        int s = g_rowptr[n], e = g_rowptr[n + 1];
        float acc = __half2float(g_zh[(long)n * OUTF + j]);
        int p = s;
        for (; p + 4 <= e; p += 4) {
            int s0 = g_csr_src[p + 0], s1 = g_csr_src[p + 1];
            int s2 = g_csr_src[p + 2], s3 = g_csr_src[p + 3];
            float z0 = __half2float(g_zh[(long)s0 * OUTF + j]);
            float z1 = __half2float(g_zh[(long)s1 * OUTF + j]);
            float z2 = __half2float(g_zh[(long)s2 * OUTF + j]);
            float z3 = __half2float(g_zh[(long)s3 * OUTF + j]);
            acc += z0 + z1 + z2 + z3;
        }
        for (; p < e; p++)
            acc += __half2float(g_zh[(long)g_csr_src[p] * OUTF + j]);
        float dn = g_dinv[n];
        float val = dn * acc + b2j;
        g_h2[(long)n * OUTF + j] = val;
        bs += val;
        bq += val * val;
    }
    atomicAdd(&g_stat2[j], bs);
    atomicAdd(&g_stat2[OUTF + j], bq);
}

// pool + BN2 affine (computed per-block from stats) + L2 normalize
__global__ __launch_bounds__(128) void k_pool(const float* __restrict__ g2,
                                              const float* __restrict__ be2,
                                              float* __restrict__ out) {
    int g = blockIdx.x;
    int j = threadIdx.x;
    float mean = g_stat2[j] / (float)N_NODES;
    float var = g_stat2[OUTF + j] / (float)N_NODES - mean * mean;
    var = fmaxf(var, 0.f);
    float sc = rsqrtf(var + BN_EPS) * g2[j];
    float sh = be2[j] - mean * sc;
    int s = g_gstart[g], e = g_gstart[g + 1];
    float acc = 0.f;
    for (int i = s; i < e; i++) acc += g_h2[(long)i * OUTF + j];
    int cnt = e - s;
    float y = 0.f;
    if (cnt > 0) {
        float p = acc / (float)cnt;
        y = p * sc + sh;
    }
    float v = y * y;
#pragma unroll
    for (int off = 16; off > 0; off >>= 1) v += __shfl_xor_sync(0xffffffffu, v, off);
    __shared__ float ws[4];
    if ((j & 31) == 0) ws[j >> 5] = v;
    __syncthreads();
    float ss = ws[0] + ws[1] + ws[2] + ws[3];
    float nrm = sqrtf(ss);
    out[g * OUTF + j] = y / fmaxf(nrm, 1e-12f);
}

// ---------------- launch ----------------
extern "C" void kernel_launch(void* const* d_in, const int* in_sizes, int n_in,
                              void* d_out, int out_size) {
    const float* x   = (const float*)d_in[0];
    const float* W1  = (const float*)d_in[1];
    const float* b1  = (const float*)d_in[2];
    const float* g1  = (const float*)d_in[3];
    const float* be1 = (const float*)d_in[4];
    const float* W2  = (const float*)d_in[5];
    const float* b2  = (const float*)d_in[6];
    const float* g2  = (const float*)d_in[7];
    const float* be2 = (const float*)d_in[8];
    const int* edge  = (const int*)d_in[9];
    const int* batch = (const int*)d_in[10];
    float* out = (float*)d_out;

    const int TB = 256;
    int nb_N = (N_NODES + TB - 1) / TB;
    int nb_E = (N_EDGES + TB - 1) / TB;

    k_init<<<nb_N, TB>>>();
    k_count<<<nb_E, TB>>>(edge);
    k_scan1<<<SCAN_NB, SCAN_B>>>();
    k_scan2<<<1, 128>>>();
    k_scan3<<<SCAN_NB, SCAN_B>>>(x);
    k_fill<<<nb_E, TB>>>(edge, batch);
    k_agg1<<<nb_N, TB>>>();
    k_gemm1<<<(N_NODES + G1_ROWS - 1) / G1_ROWS, 256>>>(W1, b1);
    k_gemm2<<<(N_NODES + TCBM - 1) / TCBM, 256>>>(W2, g1, be1);
    k_agg2<<<N_NODES / A2_NPB, 128>>>(b2);
    k_pool<<<N_GRAPHS, 128>>>(g2, be2, out);
}